// round 2
// baseline (speedup 1.0000x reference)
#include <cuda_runtime.h>
#include <cuda_bf16.h>

// Problem constants
#define N_NEURONS 80
#define TBL 256
#define LATENT 128
#define N_GRAPHS 64
#define N_NODES (N_GRAPHS * N_NEURONS)   // 5120
#define N_EDGES (N_NODES * 32)           // 163840
#define N2 (N_NEURONS * N_NEURONS)       // 6400
#define H1 (2 * N2)                      // 12800

// Scratch (device globals; no allocation allowed)
__device__ float g_h[N_NODES * LATENT];      // x @ Wg
__device__ float g_deg[N_NODES];
__device__ float g_dinv[N_NODES];
__device__ float g_agg[N_NODES * LATENT];    // scatter-add result
__device__ float g_zz[N_GRAPHS * N2];        // outer products, input to GEMM1
__device__ float g_z1[N_GRAPHS * H1];        // GEMM1 output

// ---------------------------------------------------------------------------
// Zero deg + agg
// ---------------------------------------------------------------------------
__global__ void zero_kernel() {
    int i = blockIdx.x * blockDim.x + threadIdx.x;
    int total = N_NODES * LATENT;
    if (i < total) g_agg[i] = 0.0f;
    if (i < N_NODES) g_deg[i] = 0.0f;
}

// ---------------------------------------------------------------------------
// h = x @ Wg   [5120,256] @ [256,128]
// One block = 4 nodes, 128 threads (one per output column).
// ---------------------------------------------------------------------------
__global__ __launch_bounds__(128) void gemm_h_kernel(
    const float* __restrict__ x, const float* __restrict__ Wg) {
    __shared__ float xs[4][TBL];
    int node0 = blockIdx.x * 4;
    int j = threadIdx.x;  // output column 0..127

    for (int idx = threadIdx.x; idx < 4 * TBL; idx += 128) {
        xs[idx / TBL][idx % TBL] = x[node0 * TBL + idx];
    }
    __syncthreads();

    float acc0 = 0.f, acc1 = 0.f, acc2 = 0.f, acc3 = 0.f;
#pragma unroll 4
    for (int k = 0; k < TBL; k++) {
        float w = Wg[k * LATENT + j];
        acc0 += xs[0][k] * w;
        acc1 += xs[1][k] * w;
        acc2 += xs[2][k] * w;
        acc3 += xs[3][k] * w;
    }
    g_h[(node0 + 0) * LATENT + j] = acc0;
    g_h[(node0 + 1) * LATENT + j] = acc1;
    g_h[(node0 + 2) * LATENT + j] = acc2;
    g_h[(node0 + 3) * LATENT + j] = acc3;
}

// ---------------------------------------------------------------------------
// Degree (count of incoming edges per dst)
// ---------------------------------------------------------------------------
__global__ void deg_kernel(const int* __restrict__ ei) {
    int e = blockIdx.x * blockDim.x + threadIdx.x;
    if (e < N_EDGES) {
        atomicAdd(&g_deg[ei[N_EDGES + e]], 1.0f);
    }
}

__global__ void dinv_kernel() {
    int i = blockIdx.x * blockDim.x + threadIdx.x;
    if (i < N_NODES) {
        float d = g_deg[i];
        g_dinv[i] = (d > 0.0f) ? rsqrtf(fmaxf(d, 1.0f)) : 0.0f;
    }
}

// ---------------------------------------------------------------------------
// agg[dst] += h[src] * (dinv[src]*dinv[dst])
// One warp per edge; lane handles 4 columns (float4 gather, 4 atomics).
// ---------------------------------------------------------------------------
__global__ __launch_bounds__(256) void scatter_kernel(const int* __restrict__ ei) {
    long long tid = (long long)blockIdx.x * blockDim.x + threadIdx.x;
    int e = (int)(tid >> 5);
    int lane = (int)(tid & 31);
    if (e >= N_EDGES) return;
    int s = ei[e];
    int d = ei[N_EDGES + e];
    float norm = g_dinv[s] * g_dinv[d];
    float4 v = reinterpret_cast<const float4*>(&g_h[(size_t)s * LATENT])[lane];
    float* ag = &g_agg[(size_t)d * LATENT + lane * 4];
    atomicAdd(ag + 0, v.x * norm);
    atomicAdd(ag + 1, v.y * norm);
    atomicAdd(ag + 2, v.z * norm);
    atomicAdd(ag + 3, v.w * norm);
}

// ---------------------------------------------------------------------------
// Per-graph: z = relu(agg + bg); zz[n][m] = sum_l z[n][l]*z[m][l]
// One block per graph. z tile (80x128 fp32) lives in smem (padded).
// ---------------------------------------------------------------------------
__global__ __launch_bounds__(256) void outer_kernel(const float* __restrict__ bg) {
    __shared__ float zs[N_NEURONS][LATENT + 1];
    int g = blockIdx.x;

    for (int idx = threadIdx.x; idx < N_NEURONS * LATENT; idx += 256) {
        int n = idx >> 7;
        int l = idx & 127;
        float v = g_agg[((size_t)g * N_NEURONS + n) * LATENT + l] + bg[l];
        zs[n][l] = v > 0.0f ? v : 0.0f;
    }
    __syncthreads();

    for (int p = threadIdx.x; p < N2; p += 256) {
        int n = p / N_NEURONS;
        int m = p % N_NEURONS;
        float acc = 0.0f;
#pragma unroll 8
        for (int l = 0; l < LATENT; l++) {
            acc += zs[n][l] * zs[m][l];
        }
        g_zz[(size_t)g * N2 + p] = acc;
    }
}

// ---------------------------------------------------------------------------
// Skinny GEMM: out[64,N] = epilog(A[64,K] @ W[K,N] + bias)
// Register-blocked: each thread computes RPT rows x CPT cols.
// EPILOG: 0 = relu, 1 = sigmoid
// ---------------------------------------------------------------------------
template <int NTILE, int TPB, int RPT, int CPT, int EPILOG>
__global__ __launch_bounds__(TPB) void gemm_skinny(
    const float* __restrict__ A, const float* __restrict__ W,
    const float* __restrict__ bias, float* __restrict__ out,
    int K, int N) {
    constexpr int M = 64;
    constexpr int KT = 16;
    constexpr int CG = NTILE / CPT;  // column groups
    static_assert(CG * (M / RPT) == TPB, "thread layout mismatch");

    __shared__ float a_sm[KT][M + 1];
    __shared__ float w_sm[KT][NTILE];

    int tid = threadIdx.x;
    int n0 = blockIdx.x * NTILE;
    int cg = tid % CG;
    int rg = tid / CG;  // row group: rows [rg*RPT, rg*RPT+RPT)

    float acc[RPT][CPT];
#pragma unroll
    for (int r = 0; r < RPT; r++)
#pragma unroll
        for (int c = 0; c < CPT; c++) acc[r][c] = 0.0f;

    for (int k0 = 0; k0 < K; k0 += KT) {
        // Load A chunk [64 x KT], stored transposed for broadcast reads
        for (int idx = tid; idx < M * KT; idx += TPB) {
            int r = idx / KT;
            int kk = idx % KT;
            a_sm[kk][r] = A[(size_t)r * K + k0 + kk];
        }
        // Load W chunk [KT x NTILE] (contiguous along N -> coalesced)
        for (int idx = tid; idx < KT * NTILE; idx += TPB) {
            int kk = idx / NTILE;
            int n = idx % NTILE;
            w_sm[kk][n] = W[(size_t)(k0 + kk) * N + n0 + n];
        }
        __syncthreads();

#pragma unroll
        for (int kk = 0; kk < KT; kk++) {
            float a[RPT], w[CPT];
#pragma unroll
            for (int r = 0; r < RPT; r++) a[r] = a_sm[kk][rg * RPT + r];
#pragma unroll
            for (int c = 0; c < CPT; c++) w[c] = w_sm[kk][cg + c * CG];
#pragma unroll
            for (int r = 0; r < RPT; r++)
#pragma unroll
                for (int c = 0; c < CPT; c++) acc[r][c] += a[r] * w[c];
        }
        __syncthreads();
    }

#pragma unroll
    for (int r = 0; r < RPT; r++) {
        int row = rg * RPT + r;
#pragma unroll
        for (int c = 0; c < CPT; c++) {
            int col = n0 + cg + c * CG;
            float v = acc[r][c] + bias[col];
            if (EPILOG == 0) {
                v = v > 0.0f ? v : 0.0f;
            } else {
                v = 1.0f / (1.0f + __expf(-v));
            }
            out[(size_t)row * N + col] = v;
        }
    }
}

// ---------------------------------------------------------------------------
extern "C" void kernel_launch(void* const* d_in, const int* in_sizes, int n_in,
                              void* d_out, int out_size) {
    const float* x  = (const float*)d_in[0];
    const int* ei   = (const int*)d_in[1];
    const float* Wg = (const float*)d_in[2];
    const float* bg = (const float*)d_in[3];
    const float* W1 = (const float*)d_in[4];
    const float* b1 = (const float*)d_in[5];
    const float* W2 = (const float*)d_in[6];
    const float* b2 = (const float*)d_in[7];
    float* out = (float*)d_out;

    // 1. zero deg + agg
    {
        int total = N_NODES * LATENT;
        zero_kernel<<<(total + 255) / 256, 256>>>();
    }
    // 2. h = x @ Wg
    gemm_h_kernel<<<N_NODES / 4, 128>>>(x, Wg);
    // 3. degree
    deg_kernel<<<(N_EDGES + 255) / 256, 256>>>(ei);
    // 4. dinv
    dinv_kernel<<<(N_NODES + 255) / 256, 256>>>();
    // 5. scatter-add messages
    {
        long long threads = (long long)N_EDGES * 32;
        scatter_kernel<<<(unsigned)((threads + 255) / 256), 256>>>(ei);
    }
    // 6. relu + per-graph outer product
    outer_kernel<<<N_GRAPHS, 256>>>(bg);
    // 7. z1 = relu(zz @ W1 + b1)   [64,6400]@[6400,12800]
    {
        float* z1;
        cudaGetSymbolAddress((void**)&z1, g_z1);
        float* zz;
        cudaGetSymbolAddress((void**)&zz, g_zz);
        gemm_skinny<64, 128, 8, 4, 0><<<H1 / 64, 128>>>(zz, W1, b1, z1, N2, H1);
    }
    // 8. out = sigmoid(z1 @ W2 + b2)   [64,12800]@[12800,6400]
    {
        float* z1;
        cudaGetSymbolAddress((void**)&z1, g_z1);
        gemm_skinny<32, 128, 4, 4, 1><<<N2 / 32, 128>>>(z1, W2, b2, out, H1, N2);
    }
}

// round 7
// speedup vs baseline: 4.0322x; 4.0322x over previous
#include <cuda_runtime.h>
#include <cuda_bf16.h>

// Problem constants
#define N_NEURONS 80
#define TBL 256
#define LATENT 128
#define N_GRAPHS 64
#define N_NODES (N_GRAPHS * N_NEURONS)   // 5120
#define N_EDGES (N_NODES * 32)           // 163840
#define N2 (N_NEURONS * N_NEURONS)       // 6400
#define H1 (2 * N2)                      // 12800
#define SK1 4                            // split-K for GEMM1 (K=6400 -> 1600)
#define SK2 8                            // split-K for GEMM2 (K=12800 -> 1600)

// Scratch (device globals; no allocation allowed)
__device__ float g_h[N_NODES * LATENT];      // x @ Wg
__device__ float g_deg[N_NODES];
__device__ float g_dinv[N_NODES];
__device__ float g_agg[N_NODES * LATENT];    // scatter-add result
__device__ float g_zz[N_GRAPHS * N2];        // outer products, input to GEMM1
__device__ float g_z1[N_GRAPHS * H1];        // GEMM1 output (after relu)
__device__ float g_p1[SK1 * N_GRAPHS * H1];  // GEMM1 split-K partials (13.1MB)
__device__ float g_p2[SK2 * N_GRAPHS * N2];  // GEMM2 split-K partials (13.1MB)

// ---------------------------------------------------------------------------
// cp.async helpers
// ---------------------------------------------------------------------------
__device__ __forceinline__ void cp_async16(void* smem, const void* gmem) {
    unsigned saddr = (unsigned)__cvta_generic_to_shared(smem);
    asm volatile("cp.async.cg.shared.global [%0], [%1], 16;" :: "r"(saddr), "l"(gmem));
}
__device__ __forceinline__ void cp_commit() {
    asm volatile("cp.async.commit_group;");
}
template <int N>
__device__ __forceinline__ void cp_wait() {
    asm volatile("cp.async.wait_group %0;" :: "n"(N));
}

// ---------------------------------------------------------------------------
// Zero deg + agg
// ---------------------------------------------------------------------------
__global__ void zero_kernel() {
    int i = blockIdx.x * blockDim.x + threadIdx.x;
    int total = N_NODES * LATENT;
    if (i < total) g_agg[i] = 0.0f;
    if (i < N_NODES) g_deg[i] = 0.0f;
}

// ---------------------------------------------------------------------------
// h = x @ Wg   [5120,256] @ [256,128]
// ---------------------------------------------------------------------------
__global__ __launch_bounds__(128) void gemm_h_kernel(
    const float* __restrict__ x, const float* __restrict__ Wg) {
    __shared__ float xs[4][TBL];
    int node0 = blockIdx.x * 4;
    int j = threadIdx.x;

    for (int idx = threadIdx.x; idx < 4 * TBL; idx += 128) {
        xs[idx / TBL][idx % TBL] = x[node0 * TBL + idx];
    }
    __syncthreads();

    float acc0 = 0.f, acc1 = 0.f, acc2 = 0.f, acc3 = 0.f;
#pragma unroll 4
    for (int k = 0; k < TBL; k++) {
        float w = Wg[k * LATENT + j];
        acc0 += xs[0][k] * w;
        acc1 += xs[1][k] * w;
        acc2 += xs[2][k] * w;
        acc3 += xs[3][k] * w;
    }
    g_h[(node0 + 0) * LATENT + j] = acc0;
    g_h[(node0 + 1) * LATENT + j] = acc1;
    g_h[(node0 + 2) * LATENT + j] = acc2;
    g_h[(node0 + 3) * LATENT + j] = acc3;
}

// ---------------------------------------------------------------------------
// Degree + dinv
// ---------------------------------------------------------------------------
__global__ void deg_kernel(const int* __restrict__ ei) {
    int e = blockIdx.x * blockDim.x + threadIdx.x;
    if (e < N_EDGES) atomicAdd(&g_deg[ei[N_EDGES + e]], 1.0f);
}

__global__ void dinv_kernel() {
    int i = blockIdx.x * blockDim.x + threadIdx.x;
    if (i < N_NODES) {
        float d = g_deg[i];
        g_dinv[i] = (d > 0.0f) ? rsqrtf(fmaxf(d, 1.0f)) : 0.0f;
    }
}

// ---------------------------------------------------------------------------
// agg[dst] += h[src] * (dinv[src]*dinv[dst]); one warp per edge
// ---------------------------------------------------------------------------
__global__ __launch_bounds__(256) void scatter_kernel(const int* __restrict__ ei) {
    long long tid = (long long)blockIdx.x * blockDim.x + threadIdx.x;
    int e = (int)(tid >> 5);
    int lane = (int)(tid & 31);
    if (e >= N_EDGES) return;
    int s = ei[e];
    int d = ei[N_EDGES + e];
    float norm = g_dinv[s] * g_dinv[d];
    float4 v = reinterpret_cast<const float4*>(&g_h[(size_t)s * LATENT])[lane];
    float* ag = &g_agg[(size_t)d * LATENT + lane * 4];
    atomicAdd(ag + 0, v.x * norm);
    atomicAdd(ag + 1, v.y * norm);
    atomicAdd(ag + 2, v.z * norm);
    atomicAdd(ag + 3, v.w * norm);
}

// ---------------------------------------------------------------------------
// Per-graph: z = relu(agg + bg); zz[n][m] = sum_l z[n][l]*z[m][l]
// ---------------------------------------------------------------------------
__global__ __launch_bounds__(256) void outer_kernel(const float* __restrict__ bg) {
    __shared__ float zs[N_NEURONS][LATENT + 1];
    int g = blockIdx.x;

    for (int idx = threadIdx.x; idx < N_NEURONS * LATENT; idx += 256) {
        int n = idx >> 7;
        int l = idx & 127;
        float v = g_agg[((size_t)g * N_NEURONS + n) * LATENT + l] + bg[l];
        zs[n][l] = v > 0.0f ? v : 0.0f;
    }
    __syncthreads();

    for (int p = threadIdx.x; p < N2; p += 256) {
        int n = p / N_NEURONS;
        int m = p % N_NEURONS;
        float acc = 0.0f;
#pragma unroll 8
        for (int l = 0; l < LATENT; l++) acc += zs[n][l] * zs[m][l];
        g_zz[(size_t)g * N2 + p] = acc;
    }
}

// ---------------------------------------------------------------------------
// Split-K GEMM: partial[sk][64][N] = A[64, kchunk] @ W[kchunk, N-tile]
//   BM=64 (full M), BN=128, KT=32, 256 threads.
//   Thread micro-tile: 8 rows x 4 cols. cg = tid&31 (32 col groups), rg = tid>>5.
//   Double-buffered cp.async pipeline.
// ---------------------------------------------------------------------------
#define GKT 32
#define GBN 128

__global__ __launch_bounds__(256) void gemm_splitk(
    const float* __restrict__ A, const float* __restrict__ W,
    float* __restrict__ partial, int K, int N, int Kchunk) {
    constexpr int M = 64;
    __shared__ alignas(16) float As[2][M][GKT];     // [m][k]  8KB/stage
    __shared__ alignas(16) float Ws[2][GKT][GBN];   // [k][n] 16KB/stage

    int tid = threadIdx.x;
    int n0 = blockIdx.x * GBN;
    int sk = blockIdx.y;
    int kbase = sk * Kchunk;
    int T = Kchunk / GKT;

    int cg = tid & 31;
    int rg = tid >> 5;

    float acc[8][4];
#pragma unroll
    for (int r = 0; r < 8; r++)
#pragma unroll
        for (int c = 0; c < 4; c++) acc[r][c] = 0.0f;

    // tile loader: A is 512 16B-chunks, W is 1024 16B-chunks
    auto issue_tile = [&](int s, int k0) {
#pragma unroll
        for (int i = 0; i < 2; i++) {
            int c = tid + i * 256;
            int m = c >> 3;
            int k4 = (c & 7) << 2;
            cp_async16(&As[s][m][k4], &A[(size_t)m * K + k0 + k4]);
        }
#pragma unroll
        for (int i = 0; i < 4; i++) {
            int c = tid + i * 256;
            int kk = c >> 5;
            int n4 = (c & 31) << 2;
            cp_async16(&Ws[s][kk][n4], &W[(size_t)(k0 + kk) * N + n0 + n4]);
        }
        cp_commit();
    };

    issue_tile(0, kbase);

    for (int t = 0; t < T; t++) {
        if (t + 1 < T) {
            issue_tile((t + 1) & 1, kbase + (t + 1) * GKT);
            cp_wait<1>();
        } else {
            cp_wait<0>();
        }
        __syncthreads();

        int s = t & 1;
#pragma unroll 8
        for (int kk = 0; kk < GKT; kk++) {
            float a[8];
#pragma unroll
            for (int r = 0; r < 8; r++) a[r] = As[s][rg * 8 + r][kk];
            float4 w = *reinterpret_cast<const float4*>(&Ws[s][kk][cg * 4]);
#pragma unroll
            for (int r = 0; r < 8; r++) {
                acc[r][0] += a[r] * w.x;
                acc[r][1] += a[r] * w.y;
                acc[r][2] += a[r] * w.z;
                acc[r][3] += a[r] * w.w;
            }
        }
        __syncthreads();
    }

    // store partial tile (float4 per row)
#pragma unroll
    for (int r = 0; r < 8; r++) {
        int row = rg * 8 + r;
        float4 v = make_float4(acc[r][0], acc[r][1], acc[r][2], acc[r][3]);
        *reinterpret_cast<float4*>(
            &partial[((size_t)sk * M + row) * N + n0 + cg * 4]) = v;
    }
}

// ---------------------------------------------------------------------------
// Epilogs: sum split-K partials + bias + activation (vectorized float4)
// ---------------------------------------------------------------------------
__global__ __launch_bounds__(256) void epilog1_kernel(const float* __restrict__ b1) {
    int i = blockIdx.x * blockDim.x + threadIdx.x;  // float4 index
    int total4 = N_GRAPHS * H1 / 4;
    if (i >= total4) return;
    const float4* p = reinterpret_cast<const float4*>(g_p1);
    float4 s = p[i];
#pragma unroll
    for (int sk = 1; sk < SK1; sk++) {
        float4 v = p[(size_t)sk * total4 + i];
        s.x += v.x; s.y += v.y; s.z += v.z; s.w += v.w;
    }
    int col = (i * 4) % H1;
    float4 b = *reinterpret_cast<const float4*>(&b1[col]);
    s.x = fmaxf(s.x + b.x, 0.0f);
    s.y = fmaxf(s.y + b.y, 0.0f);
    s.z = fmaxf(s.z + b.z, 0.0f);
    s.w = fmaxf(s.w + b.w, 0.0f);
    reinterpret_cast<float4*>(g_z1)[i] = s;
}

__global__ __launch_bounds__(256) void epilog2_kernel(const float* __restrict__ b2,
                                                      float* __restrict__ out) {
    int i = blockIdx.x * blockDim.x + threadIdx.x;  // float4 index
    int total4 = N_GRAPHS * N2 / 4;
    if (i >= total4) return;
    const float4* p = reinterpret_cast<const float4*>(g_p2);
    float4 s = p[i];
#pragma unroll
    for (int sk = 1; sk < SK2; sk++) {
        float4 v = p[(size_t)sk * total4 + i];
        s.x += v.x; s.y += v.y; s.z += v.z; s.w += v.w;
    }
    int col = (i * 4) % N2;
    float4 b = *reinterpret_cast<const float4*>(&b2[col]);
    s.x = 1.0f / (1.0f + __expf(-(s.x + b.x)));
    s.y = 1.0f / (1.0f + __expf(-(s.y + b.y)));
    s.z = 1.0f / (1.0f + __expf(-(s.z + b.z)));
    s.w = 1.0f / (1.0f + __expf(-(s.w + b.w)));
    reinterpret_cast<float4*>(out)[i] = s;
}

// ---------------------------------------------------------------------------
extern "C" void kernel_launch(void* const* d_in, const int* in_sizes, int n_in,
                              void* d_out, int out_size) {
    const float* x  = (const float*)d_in[0];
    const int* ei   = (const int*)d_in[1];
    const float* Wg = (const float*)d_in[2];
    const float* bg = (const float*)d_in[3];
    const float* W1 = (const float*)d_in[4];
    const float* b1 = (const float*)d_in[5];
    const float* W2 = (const float*)d_in[6];
    const float* b2 = (const float*)d_in[7];
    float* out = (float*)d_out;

    float *zz, *z1, *p1, *p2;
    cudaGetSymbolAddress((void**)&zz, g_zz);
    cudaGetSymbolAddress((void**)&z1, g_z1);
    cudaGetSymbolAddress((void**)&p1, g_p1);
    cudaGetSymbolAddress((void**)&p2, g_p2);

    // 1. zero deg + agg
    {
        int total = N_NODES * LATENT;
        zero_kernel<<<(total + 255) / 256, 256>>>();
    }
    // 2. h = x @ Wg
    gemm_h_kernel<<<N_NODES / 4, 128>>>(x, Wg);
    // 3. degree
    deg_kernel<<<(N_EDGES + 255) / 256, 256>>>(ei);
    // 4. dinv
    dinv_kernel<<<(N_NODES + 255) / 256, 256>>>();
    // 5. scatter-add messages
    {
        long long threads = (long long)N_EDGES * 32;
        scatter_kernel<<<(unsigned)((threads + 255) / 256), 256>>>(ei);
    }
    // 6. relu + per-graph outer product
    outer_kernel<<<N_GRAPHS, 256>>>(bg);
    // 7. GEMM1 partials: [64,6400]@[6400,12800], split-K=4 -> 400 blocks
    {
        dim3 grid(H1 / GBN, SK1);
        gemm_splitk<<<grid, 256>>>(zz, W1, p1, N2, H1, N2 / SK1);
    }
    // 8. z1 = relu(sum + b1)
    {
        int total4 = N_GRAPHS * H1 / 4;
        epilog1_kernel<<<(total4 + 255) / 256, 256>>>(b1);
    }
    // 9. GEMM2 partials: [64,12800]@[12800,6400], split-K=8 -> 400 blocks
    {
        dim3 grid(N2 / GBN, SK2);
        gemm_splitk<<<grid, 256>>>(z1, W2, p2, H1, N2, H1 / SK2);
    }
    // 10. out = sigmoid(sum + b2)
    {
        int total4 = N_GRAPHS * N2 / 4;
        epilog2_kernel<<<(total4 + 255) / 256, 256>>>(b2, out);
    }
}

// round 10
// speedup vs baseline: 8.8406x; 2.1925x over previous
#include <cuda_runtime.h>
#include <cuda_bf16.h>
#include <cstdint>

// Problem constants
#define N_NEURONS 80
#define TBL 256
#define LATENT 128
#define N_GRAPHS 64
#define N_NODES (N_GRAPHS * N_NEURONS)   // 5120
#define N_EDGES (N_NODES * 32)           // 163840
#define N2 (N_NEURONS * N_NEURONS)       // 6400
#define H1 (2 * N2)                      // 12800
#define SK1 4                            // split-K for GEMM1
#define SK2 8                            // split-K for GEMM2

// Scratch (device globals; no allocation allowed)
__device__ float g_h[N_NODES * LATENT];
__device__ float g_deg[N_NODES];
__device__ float g_dinv[N_NODES];
__device__ float g_agg[N_NODES * LATENT];
__device__ float g_zz[N_GRAPHS * N2];
__device__ float g_z1[N_GRAPHS * H1];
__device__ float g_p1[SK1 * N_GRAPHS * H1];
__device__ float g_p2[SK2 * N_GRAPHS * N2];

// ---------------------------------------------------------------------------
// cp.async helpers
// ---------------------------------------------------------------------------
__device__ __forceinline__ void cp_async16(void* smem, const void* gmem) {
    unsigned saddr = (unsigned)__cvta_generic_to_shared(smem);
    asm volatile("cp.async.cg.shared.global [%0], [%1], 16;" :: "r"(saddr), "l"(gmem));
}
__device__ __forceinline__ void cp_commit() {
    asm volatile("cp.async.commit_group;");
}
template <int N>
__device__ __forceinline__ void cp_wait() {
    asm volatile("cp.async.wait_group %0;" :: "n"(N));
}

// ---------------------------------------------------------------------------
// mma / ldmatrix helpers
// ---------------------------------------------------------------------------
__device__ __forceinline__ void ldm_x4(uint32_t* r, const void* p) {
    uint32_t a = (uint32_t)__cvta_generic_to_shared(p);
    asm volatile("ldmatrix.sync.aligned.m8n8.x4.shared.b16 {%0,%1,%2,%3}, [%4];"
        : "=r"(r[0]), "=r"(r[1]), "=r"(r[2]), "=r"(r[3]) : "r"(a));
}
__device__ __forceinline__ void ldm_x4_t(uint32_t* r, const void* p) {
    uint32_t a = (uint32_t)__cvta_generic_to_shared(p);
    asm volatile("ldmatrix.sync.aligned.m8n8.x4.trans.shared.b16 {%0,%1,%2,%3}, [%4];"
        : "=r"(r[0]), "=r"(r[1]), "=r"(r[2]), "=r"(r[3]) : "r"(a));
}
__device__ __forceinline__ void mma_bf16(float* c, const uint32_t* a, const uint32_t* b) {
    asm volatile(
        "mma.sync.aligned.m16n8k16.row.col.f32.bf16.bf16.f32 "
        "{%0,%1,%2,%3}, {%4,%5,%6,%7}, {%8,%9}, {%0,%1,%2,%3};"
        : "+f"(c[0]), "+f"(c[1]), "+f"(c[2]), "+f"(c[3])
        : "r"(a[0]), "r"(a[1]), "r"(a[2]), "r"(a[3]), "r"(b[0]), "r"(b[1]));
}

// ---------------------------------------------------------------------------
// Zero deg + agg
// ---------------------------------------------------------------------------
__global__ void zero_kernel() {
    int i = blockIdx.x * blockDim.x + threadIdx.x;
    int total = N_NODES * LATENT;
    if (i < total) g_agg[i] = 0.0f;
    if (i < N_NODES) g_deg[i] = 0.0f;
}

// ---------------------------------------------------------------------------
// h = x @ Wg   [5120,256] @ [256,128]
// ---------------------------------------------------------------------------
__global__ __launch_bounds__(128) void gemm_h_kernel(
    const float* __restrict__ x, const float* __restrict__ Wg) {
    __shared__ float xs[4][TBL];
    int node0 = blockIdx.x * 4;
    int j = threadIdx.x;

    for (int idx = threadIdx.x; idx < 4 * TBL; idx += 128) {
        xs[idx / TBL][idx % TBL] = x[node0 * TBL + idx];
    }
    __syncthreads();

    float acc0 = 0.f, acc1 = 0.f, acc2 = 0.f, acc3 = 0.f;
#pragma unroll 4
    for (int k = 0; k < TBL; k++) {
        float w = Wg[k * LATENT + j];
        acc0 += xs[0][k] * w;
        acc1 += xs[1][k] * w;
        acc2 += xs[2][k] * w;
        acc3 += xs[3][k] * w;
    }
    g_h[(node0 + 0) * LATENT + j] = acc0;
    g_h[(node0 + 1) * LATENT + j] = acc1;
    g_h[(node0 + 2) * LATENT + j] = acc2;
    g_h[(node0 + 3) * LATENT + j] = acc3;
}

// ---------------------------------------------------------------------------
// Degree + dinv
// ---------------------------------------------------------------------------
__global__ void deg_kernel(const int* __restrict__ ei) {
    int e = blockIdx.x * blockDim.x + threadIdx.x;
    if (e < N_EDGES) atomicAdd(&g_deg[ei[N_EDGES + e]], 1.0f);
}

__global__ void dinv_kernel() {
    int i = blockIdx.x * blockDim.x + threadIdx.x;
    if (i < N_NODES) {
        float d = g_deg[i];
        g_dinv[i] = (d > 0.0f) ? rsqrtf(fmaxf(d, 1.0f)) : 0.0f;
    }
}

// ---------------------------------------------------------------------------
// agg[dst] += h[src] * (dinv[src]*dinv[dst]); one warp per edge
// ---------------------------------------------------------------------------
__global__ __launch_bounds__(256) void scatter_kernel(const int* __restrict__ ei) {
    long long tid = (long long)blockIdx.x * blockDim.x + threadIdx.x;
    int e = (int)(tid >> 5);
    int lane = (int)(tid & 31);
    if (e >= N_EDGES) return;
    int s = ei[e];
    int d = ei[N_EDGES + e];
    float norm = g_dinv[s] * g_dinv[d];
    float4 v = reinterpret_cast<const float4*>(&g_h[(size_t)s * LATENT])[lane];
    float* ag = &g_agg[(size_t)d * LATENT + lane * 4];
    atomicAdd(ag + 0, v.x * norm);
    atomicAdd(ag + 1, v.y * norm);
    atomicAdd(ag + 2, v.z * norm);
    atomicAdd(ag + 3, v.w * norm);
}

// ---------------------------------------------------------------------------
// Per-graph: z = relu(agg + bg); zz[n][m] = sum_l z[n][l]*z[m][l]
// ---------------------------------------------------------------------------
__global__ __launch_bounds__(256) void outer_kernel(const float* __restrict__ bg) {
    __shared__ float zs[N_NEURONS][LATENT + 1];
    int g = blockIdx.x;

    for (int idx = threadIdx.x; idx < N_NEURONS * LATENT; idx += 256) {
        int n = idx >> 7;
        int l = idx & 127;
        float v = g_agg[((size_t)g * N_NEURONS + n) * LATENT + l] + bg[l];
        zs[n][l] = v > 0.0f ? v : 0.0f;
    }
    __syncthreads();

    for (int p = threadIdx.x; p < N2; p += 256) {
        int n = p / N_NEURONS;
        int m = p % N_NEURONS;
        float acc = 0.0f;
#pragma unroll 8
        for (int l = 0; l < LATENT; l++) acc += zs[n][l] * zs[m][l];
        g_zz[(size_t)g * N2 + p] = acc;
    }
}

// ---------------------------------------------------------------------------
// Tensor-core split-K GEMM with bf16 hi/lo 3-term split (~fp32 accuracy).
//   partial[sk][64][N] = A[64, Kchunk] @ W[Kchunk, BN-tile]
//   BM=64, BN=128, 256 threads = 8 warps; warp grid 2(m)x4(n), warp tile 32x32.
//   Per fp32 k-step of 16: smem holds 48 bf16 k-slots:
//     A phases [hi | lo | hi]   vs   W phases [hi | hi | lo]
//   => A_hi*W_hi + A_lo*W_hi + A_hi*W_lo  (lo*lo dropped, ~2^-17 rel err)
// ---------------------------------------------------------------------------
#define BM 64
#define BN 128
#define KTO 16          // fp32 k per iteration
#define KTR 48          // tripled bf16 k per iteration
#define AS_STRIDE 56    // bf16 halves per A_sm row (112B: conflict-free ldmatrix)
#define WS_STRIDE 136   // bf16 halves per W_sm row (272B: conflict-free ldmatrix)

__global__ __launch_bounds__(256) void gemm_mma_splitk(
    const float* __restrict__ A, const float* __restrict__ W,
    float* __restrict__ partial, int K, int N, int Kchunk) {
    __shared__ __nv_bfloat16 A_sm[BM][AS_STRIDE];            // 7168 B
    __shared__ __nv_bfloat16 W_sm[KTR][WS_STRIDE];           // 13056 B
    __shared__ alignas(16) float As_stage[2][BM][KTO];       // 8192 B
    __shared__ alignas(16) float Ws_stage[2][KTO][BN];       // 16384 B

    int tid = threadIdx.x;
    int wid = tid >> 5, lane = tid & 31;
    int warp_m = wid & 1;        // rows 32*warp_m .. +31
    int warp_n = wid >> 1;       // cols 32*warp_n .. +31
    int n0 = blockIdx.x * BN;
    int sk = blockIdx.y;
    int kbase = sk * Kchunk;
    int T = Kchunk / KTO;

    float acc[2][4][4];
#pragma unroll
    for (int mi = 0; mi < 2; mi++)
#pragma unroll
        for (int ni = 0; ni < 4; ni++)
#pragma unroll
            for (int c = 0; c < 4; c++) acc[mi][ni][c] = 0.0f;

    auto issue = [&](int s, int k0) {
        // A tile: 64 rows x 16 floats = 256 16B-chunks
        {
            int m = tid >> 2, c = tid & 3;
            cp_async16(&As_stage[s][m][c * 4], &A[(size_t)m * K + k0 + c * 4]);
        }
        // W tile: 16 rows x 128 floats = 512 16B-chunks
#pragma unroll
        for (int i = 0; i < 2; i++) {
            int c = tid + i * 256;
            int kk = c >> 5, n4 = (c & 31) * 4;
            cp_async16(&Ws_stage[s][kk][n4], &W[(size_t)(k0 + kk) * N + n0 + n4]);
        }
        cp_commit();
    };

    issue(0, kbase);

    // ldmatrix lane addressing (shared by A and B patterns)
    int g8 = lane >> 3, r8 = lane & 7;
    int row_off = (g8 & 1) * 8 + r8;
    int col_off = (g8 >> 1) * 8;

    for (int t = 0; t < T; t++) {
        if (t + 1 < T) {
            issue((t + 1) & 1, kbase + (t + 1) * KTO);
            cp_wait<1>();
        } else {
            cp_wait<0>();
        }
        __syncthreads();  // stage ready + previous mma done

        int s = t & 1;
        // Convert A: 512 float2 pairs -> 2 per thread
#pragma unroll
        for (int i = 0; i < 2; i++) {
            int idx = tid + i * 256;
            int m = idx >> 3, kp = idx & 7;
            float2 f = *reinterpret_cast<const float2*>(&As_stage[s][m][kp * 2]);
            __nv_bfloat162 hi = __floats2bfloat162_rn(f.x, f.y);
            __nv_bfloat162 lo = __floats2bfloat162_rn(
                f.x - __bfloat162float(hi.x), f.y - __bfloat162float(hi.y));
            *(__nv_bfloat162*)&A_sm[m][kp * 2]      = hi;
            *(__nv_bfloat162*)&A_sm[m][16 + kp * 2] = lo;
            *(__nv_bfloat162*)&A_sm[m][32 + kp * 2] = hi;
        }
        // Convert W: 1024 float2 pairs -> 4 per thread
#pragma unroll
        for (int i = 0; i < 4; i++) {
            int idx = tid + i * 256;
            int kk = idx >> 6, np = idx & 63;
            float2 f = *reinterpret_cast<const float2*>(&Ws_stage[s][kk][np * 2]);
            __nv_bfloat162 hi = __floats2bfloat162_rn(f.x, f.y);
            __nv_bfloat162 lo = __floats2bfloat162_rn(
                f.x - __bfloat162float(hi.x), f.y - __bfloat162float(hi.y));
            *(__nv_bfloat162*)&W_sm[kk][np * 2]      = hi;
            *(__nv_bfloat162*)&W_sm[16 + kk][np * 2] = hi;
            *(__nv_bfloat162*)&W_sm[32 + kk][np * 2] = lo;
        }
        __syncthreads();  // bf16 tiles ready

#pragma unroll
        for (int p = 0; p < 3; p++) {
            uint32_t afr[2][4], bfr[2][4];
#pragma unroll
            for (int mi = 0; mi < 2; mi++)
                ldm_x4(afr[mi], &A_sm[warp_m * 32 + mi * 16 + row_off][p * 16 + col_off]);
#pragma unroll
            for (int ni = 0; ni < 2; ni++)
                ldm_x4_t(bfr[ni], &W_sm[p * 16 + row_off][warp_n * 32 + ni * 16 + col_off]);
#pragma unroll
            for (int mi = 0; mi < 2; mi++) {
                mma_bf16(acc[mi][0], afr[mi], &bfr[0][0]);
                mma_bf16(acc[mi][1], afr[mi], &bfr[0][2]);
                mma_bf16(acc[mi][2], afr[mi], &bfr[1][0]);
                mma_bf16(acc[mi][3], afr[mi], &bfr[1][2]);
            }
        }
        __syncthreads();  // bf16 consumed before next convert
    }

    // Store partial tile (fp32). C fragment: c0=(g,2c) c1=(g,2c+1) c2=(g+8,2c) c3=(g+8,2c+1)
    int gq = lane >> 2, c2 = (lane & 3) * 2;
#pragma unroll
    for (int mi = 0; mi < 2; mi++)
#pragma unroll
        for (int ni = 0; ni < 4; ni++) {
            int col = n0 + warp_n * 32 + ni * 8 + c2;
            int row0 = warp_m * 32 + mi * 16 + gq;
            float* base = &partial[((size_t)sk * BM + row0) * N + col];
            *reinterpret_cast<float2*>(base) =
                make_float2(acc[mi][ni][0], acc[mi][ni][1]);
            *reinterpret_cast<float2*>(base + 8 * (size_t)N) =
                make_float2(acc[mi][ni][2], acc[mi][ni][3]);
        }
}

// ---------------------------------------------------------------------------
// Epilogs: sum split-K partials + bias + activation
// ---------------------------------------------------------------------------
__global__ __launch_bounds__(256) void epilog1_kernel(const float* __restrict__ b1) {
    int i = blockIdx.x * blockDim.x + threadIdx.x;
    int total4 = N_GRAPHS * H1 / 4;
    if (i >= total4) return;
    const float4* p = reinterpret_cast<const float4*>(g_p1);
    float4 s = p[i];
#pragma unroll
    for (int sk = 1; sk < SK1; sk++) {
        float4 v = p[(size_t)sk * total4 + i];
        s.x += v.x; s.y += v.y; s.z += v.z; s.w += v.w;
    }
    int col = (i * 4) % H1;
    float4 b = *reinterpret_cast<const float4*>(&b1[col]);
    s.x = fmaxf(s.x + b.x, 0.0f);
    s.y = fmaxf(s.y + b.y, 0.0f);
    s.z = fmaxf(s.z + b.z, 0.0f);
    s.w = fmaxf(s.w + b.w, 0.0f);
    reinterpret_cast<float4*>(g_z1)[i] = s;
}

__global__ __launch_bounds__(256) void epilog2_kernel(const float* __restrict__ b2,
                                                      float* __restrict__ out) {
    int i = blockIdx.x * blockDim.x + threadIdx.x;
    int total4 = N_GRAPHS * N2 / 4;
    if (i >= total4) return;
    const float4* p = reinterpret_cast<const float4*>(g_p2);
    float4 s = p[i];
#pragma unroll
    for (int sk = 1; sk < SK2; sk++) {
        float4 v = p[(size_t)sk * total4 + i];
        s.x += v.x; s.y += v.y; s.z += v.z; s.w += v.w;
    }
    int col = (i * 4) % N2;
    float4 b = *reinterpret_cast<const float4*>(&b2[col]);
    s.x = 1.0f / (1.0f + __expf(-(s.x + b.x)));
    s.y = 1.0f / (1.0f + __expf(-(s.y + b.y)));
    s.z = 1.0f / (1.0f + __expf(-(s.z + b.z)));
    s.w = 1.0f / (1.0f + __expf(-(s.w + b.w)));
    reinterpret_cast<float4*>(out)[i] = s;
}

// ---------------------------------------------------------------------------
extern "C" void kernel_launch(void* const* d_in, const int* in_sizes, int n_in,
                              void* d_out, int out_size) {
    const float* x  = (const float*)d_in[0];
    const int* ei   = (const int*)d_in[1];
    const float* Wg = (const float*)d_in[2];
    const float* bg = (const float*)d_in[3];
    const float* W1 = (const float*)d_in[4];
    const float* b1 = (const float*)d_in[5];
    const float* W2 = (const float*)d_in[6];
    const float* b2 = (const float*)d_in[7];
    float* out = (float*)d_out;

    float *zz, *z1, *p1, *p2;
    cudaGetSymbolAddress((void**)&zz, g_zz);
    cudaGetSymbolAddress((void**)&z1, g_z1);
    cudaGetSymbolAddress((void**)&p1, g_p1);
    cudaGetSymbolAddress((void**)&p2, g_p2);

    // 1. zero deg + agg
    {
        int total = N_NODES * LATENT;
        zero_kernel<<<(total + 255) / 256, 256>>>();
    }
    // 2. h = x @ Wg
    gemm_h_kernel<<<N_NODES / 4, 128>>>(x, Wg);
    // 3. degree
    deg_kernel<<<(N_EDGES + 255) / 256, 256>>>(ei);
    // 4. dinv
    dinv_kernel<<<(N_NODES + 255) / 256, 256>>>();
    // 5. scatter-add messages
    {
        long long threads = (long long)N_EDGES * 32;
        scatter_kernel<<<(unsigned)((threads + 255) / 256), 256>>>(ei);
    }
    // 6. relu + per-graph outer product
    outer_kernel<<<N_GRAPHS, 256>>>(bg);
    // 7. GEMM1 partials: [64,6400]@[6400,12800], split-K=4 -> 400 blocks
    {
        dim3 grid(H1 / BN, SK1);
        gemm_mma_splitk<<<grid, 256>>>(zz, W1, p1, N2, H1, N2 / SK1);
    }
    // 8. z1 = relu(sum + b1)
    {
        int total4 = N_GRAPHS * H1 / 4;
        epilog1_kernel<<<(total4 + 255) / 256, 256>>>(b1);
    }
    // 9. GEMM2 partials: [64,12800]@[12800,6400], split-K=8 -> 400 blocks
    {
        dim3 grid(N2 / BN, SK2);
        gemm_mma_splitk<<<grid, 256>>>(z1, W2, p2, H1, N2, H1 / SK2);
    }
    // 10. out = sigmoid(sum + b2)
    {
        int total4 = N_GRAPHS * N2 / 4;
        epilog2_kernel<<<(total4 + 255) / 256, 256>>>(b2, out);
    }
}